// round 1
// baseline (speedup 1.0000x reference)
#include <cuda_runtime.h>
#include <cuda_bf16.h>

// QuantumCBOW: B=16384, S=10, DIM=8, TRIL=36.
// out[b] = -log(clip(F(ctx_rho[b], tgt_rho[b]), 1e-8, 1))
//
// Analytical simplifications vs reference:
//  * corr in _compute_density is always exactly 1e-6 (rho = LL^T + eps I is PSD),
//    so density = (LL^T + 2e-6 I) / (tr(LL^T) + 1.7e-5). No eigvalsh needed.
//  * sqrt_rho = (rho + eps I)^{1/2}; eig(sqrt_rho sigma sqrt_rho) = eig(C^T sigma C)
//    with rho + eps I = C C^T (Cholesky). Only ONE eigenvalue-only 8x8 Jacobi
//    solve per batch element.

#define QC_DIM  8
#define QC_TRIL 36
#define QC_S    10

__device__ __forceinline__ constexpr int sidx(int i, int j) { return i * (i + 1) / 2 + j; }
__device__ __forceinline__ constexpr int symi(int i, int j) { return (i >= j) ? sidx(i, j) : sidx(j, i); }

// Accumulate the normalized density matrix of one token (36 params) into acc[36].
__device__ __forceinline__ void add_density(const float* __restrict__ row, float* acc) {
    float L[QC_TRIL];
    const float4* r4 = reinterpret_cast<const float4*>(row);  // 36*4B rows, 16B aligned
#pragma unroll
    for (int v = 0; v < 9; v++) {
        float4 t = r4[v];
        L[4 * v + 0] = t.x; L[4 * v + 1] = t.y;
        L[4 * v + 2] = t.z; L[4 * v + 3] = t.w;
    }
    // clamp diagonal >= 1e-4
#pragma unroll
    for (int i = 0; i < QC_DIM; i++) {
        const int d = sidx(i, i);
        L[d] = fmaxf(L[d], 1e-4f);
    }
    // trace(L L^T) = sum of squares of all lower-tri entries
    float tr = 0.f;
#pragma unroll
    for (int i = 0; i < QC_TRIL; i++) tr = fmaf(L[i], L[i], tr);
    const float inv = 1.0f / (tr + 1.7e-5f);  // tr + 8*(eps+corr) + eps
    // rho_ij = sum_{k<=min(i,j)} L[i][k]*L[j][k]; lower storage i>=j
#pragma unroll
    for (int i = 0; i < QC_DIM; i++) {
#pragma unroll
        for (int j = 0; j <= i; j++) {
            float s = 0.f;
#pragma unroll
            for (int k = 0; k <= j; k++)
                s = fmaf(L[sidx(i, k)], L[sidx(j, k)], s);
            if (i == j) s += 2e-6f;  // eps + corr on the diagonal
            acc[sidx(i, j)] = fmaf(s, inv, acc[sidx(i, j)]);
        }
    }
}

__global__ void __launch_bounds__(128)
qcbow_kernel(const int* __restrict__ contexts,
             const int* __restrict__ targets,
             const float* __restrict__ emb,
             float* __restrict__ out,
             int B) {
    const int b = blockIdx.x * blockDim.x + threadIdx.x;
    if (b >= B) return;

    // ---- context rho: masked mean of per-token densities ----
    float ctx[QC_TRIL];
#pragma unroll
    for (int i = 0; i < QC_TRIL; i++) ctx[i] = 0.f;
    float cnt = 0.f;
#pragma unroll 1
    for (int t = 0; t < QC_S; t++) {
        const int tok = contexts[b * QC_S + t];
        if (tok != 0) {
            cnt += 1.f;
            add_density(emb + (long)tok * QC_TRIL, ctx);
        }
    }
    {
        const float ic = 1.0f / cnt;  // cnt==0 -> inf/NaN, matches reference 0/0
#pragma unroll
        for (int i = 0; i < QC_TRIL; i++) ctx[i] *= ic;
    }

    // ---- target sigma ----
    float sig[QC_TRIL];
#pragma unroll
    for (int i = 0; i < QC_TRIL; i++) sig[i] = 0.f;
    add_density(emb + (long)targets[b] * QC_TRIL, sig);

    // ---- Cholesky of (ctx + 1e-6 I): C C^T ----
    float C[QC_TRIL];
#pragma unroll
    for (int j = 0; j < QC_DIM; j++) {
        float d = ctx[sidx(j, j)] + 1e-6f;
#pragma unroll
        for (int k = 0; k < j; k++) d = fmaf(-C[sidx(j, k)], C[sidx(j, k)], d);
        const float cjj = sqrtf(fmaxf(d, 1e-14f));
        C[sidx(j, j)] = cjj;
        const float icjj = 1.0f / cjj;
#pragma unroll
        for (int i = j + 1; i < QC_DIM; i++) {
            float v = ctx[sidx(i, j)];
#pragma unroll
            for (int k = 0; k < j; k++) v = fmaf(-C[sidx(i, k)], C[sidx(j, k)], v);
            C[sidx(i, j)] = v * icjj;
        }
    }

    // ---- W = C^T * sigma * C  (symmetric PSD; eig(W) = eig((ctx+eps I) sigma)) ----
    float T[QC_DIM][QC_DIM];  // T = sigma * C
#pragma unroll
    for (int i = 0; i < QC_DIM; i++) {
#pragma unroll
        for (int j = 0; j < QC_DIM; j++) {
            float s = 0.f;
#pragma unroll
            for (int k = j; k < QC_DIM; k++)     // C[k][j] nonzero for k>=j
                s = fmaf(sig[symi(i, k)], C[sidx(k, j)], s);
            T[i][j] = s;
        }
    }
    float W[QC_DIM][QC_DIM];
#pragma unroll
    for (int i = 0; i < QC_DIM; i++) {
#pragma unroll
        for (int j = 0; j <= i; j++) {
            float s = 0.f;
#pragma unroll
            for (int k = i; k < QC_DIM; k++)     // C[k][i] nonzero for k>=i
                s = fmaf(C[sidx(k, i)], T[k][j], s);
            W[i][j] = s;
            W[j][i] = s;
        }
    }

    // ---- eigenvalues-only cyclic Jacobi (fully unrolled pairs -> registers) ----
#pragma unroll 1
    for (int sweep = 0; sweep < 8; sweep++) {
#pragma unroll
        for (int p = 0; p < QC_DIM - 1; p++) {
#pragma unroll
            for (int q = p + 1; q < QC_DIM; q++) {
                const float apq = W[p][q];
                if (fabsf(apq) > 1e-12f) {
                    const float app = W[p][p];
                    const float aqq = W[q][q];
                    const float theta = (aqq - app) / (2.0f * apq);
                    const float t = copysignf(1.0f, theta) /
                                    (fabsf(theta) + sqrtf(fmaf(theta, theta, 1.0f)));
                    const float c = rsqrtf(fmaf(t, t, 1.0f));
                    const float s = t * c;
                    // rows p,q
#pragma unroll
                    for (int k = 0; k < QC_DIM; k++) {
                        const float wpk = W[p][k];
                        const float wqk = W[q][k];
                        W[p][k] = fmaf(c, wpk, -s * wqk);
                        W[q][k] = fmaf(s, wpk,  c * wqk);
                    }
                    // cols p,q
#pragma unroll
                    for (int k = 0; k < QC_DIM; k++) {
                        const float wkp = W[k][p];
                        const float wkq = W[k][q];
                        W[k][p] = fmaf(c, wkp, -s * wkq);
                        W[k][q] = fmaf(s, wkp,  c * wkq);
                    }
                }
            }
        }
    }

    // ---- f = sum sqrt(|eig| + eps); out = -log(clip(f)) ----
    float f = 0.f;
#pragma unroll
    for (int i = 0; i < QC_DIM; i++) f += sqrtf(fabsf(W[i][i]) + 1e-6f);
    f = fminf(f, 1.0f);
    f = fmaxf(f, 1e-8f);
    out[b] = -logf(f);
}

extern "C" void kernel_launch(void* const* d_in, const int* in_sizes, int n_in,
                              void* d_out, int out_size) {
    const int*   contexts = (const int*)d_in[0];   // [B, 10] int32
    const int*   targets  = (const int*)d_in[1];   // [B] int32
    const float* emb      = (const float*)d_in[2]; // [V, 36] float32
    float*       out      = (float*)d_out;         // [B] float32
    const int B = in_sizes[1];
    const int threads = 128;
    const int blocks = (B + threads - 1) / threads;
    qcbow_kernel<<<blocks, threads>>>(contexts, targets, emb, out, B);
}

// round 2
// speedup vs baseline: 1.1832x; 1.1832x over previous
#include <cuda_runtime.h>
#include <cuda_bf16.h>

// QuantumCBOW: B=16384, S=10, DIM=8, TRIL=36.
// Latency-bound (512 warps total). This version attacks the serial chain:
//  * round-robin Jacobi ordering -> 4 independent rotations per round (ILP 4)
//  * branchless rotations with MUFU intrinsics (__fdividef / rsqrtf)
//  * 6 sweeps instead of 8
//  * branchless masked context accumulation, unroll-2 for load MLP

#define QC_DIM  8
#define QC_TRIL 36
#define QC_S    10

__device__ __forceinline__ constexpr int sidx(int i, int j) { return i * (i + 1) / 2 + j; }
__device__ __forceinline__ constexpr int symi(int i, int j) { return (i >= j) ? sidx(i, j) : sidx(j, i); }

// Accumulate w * normalized-density(row) into acc[36] (lower-tri storage).
__device__ __forceinline__ void add_density(const float* __restrict__ row, float* acc, float wgt) {
    float L[QC_TRIL];
    const float4* r4 = reinterpret_cast<const float4*>(row);  // 36*4B rows, 16B aligned
#pragma unroll
    for (int v = 0; v < 9; v++) {
        float4 t = r4[v];
        L[4 * v + 0] = t.x; L[4 * v + 1] = t.y;
        L[4 * v + 2] = t.z; L[4 * v + 3] = t.w;
    }
#pragma unroll
    for (int i = 0; i < QC_DIM; i++) {
        const int d = sidx(i, i);
        L[d] = fmaxf(L[d], 1e-4f);
    }
    float tr = 0.f;
#pragma unroll
    for (int i = 0; i < QC_TRIL; i++) tr = fmaf(L[i], L[i], tr);
    const float inv = wgt * __fdividef(1.0f, tr + 1.7e-5f);
#pragma unroll
    for (int i = 0; i < QC_DIM; i++) {
#pragma unroll
        for (int j = 0; j <= i; j++) {
            float s = 0.f;
#pragma unroll
            for (int k = 0; k <= j; k++)
                s = fmaf(L[sidx(i, k)], L[sidx(j, k)], s);
            if (i == j) s += 2e-6f;  // eps + corr
            acc[sidx(i, j)] = fmaf(s, inv, acc[sidx(i, j)]);
        }
    }
}

// Branchless Jacobi rotation on full 8x8 W, pair (p,q). Safe at apq==0, d==0.
#define JROT(p, q) do {                                                        \
    const float apq = W[p][q];                                                 \
    const float dd  = W[q][q] - W[p][p];                                       \
    const float a2  = 2.0f * apq;                                              \
    const float v   = fmaf(dd, dd, fmaf(a2, a2, 1e-30f));                      \
    const float u   = v * rsqrtf(v);                                           \
    const float t   = __fdividef(a2 * copysignf(1.0f, dd), fabsf(dd) + u);     \
    const float c   = rsqrtf(fmaf(t, t, 1.0f));                                \
    const float s   = t * c;                                                   \
    _Pragma("unroll")                                                          \
    for (int k = 0; k < QC_DIM; k++) {                                         \
        const float wpk = W[p][k], wqk = W[q][k];                              \
        W[p][k] = fmaf(c, wpk, -s * wqk);                                      \
        W[q][k] = fmaf(s, wpk,  c * wqk);                                      \
    }                                                                          \
    _Pragma("unroll")                                                          \
    for (int k = 0; k < QC_DIM; k++) {                                         \
        const float wkp = W[k][p], wkq = W[k][q];                              \
        W[k][p] = fmaf(c, wkp, -s * wkq);                                      \
        W[k][q] = fmaf(s, wkp,  c * wkq);                                      \
    }                                                                          \
} while (0)

__global__ void __launch_bounds__(128, 1)
qcbow_kernel(const int* __restrict__ contexts,
             const int* __restrict__ targets,
             const float* __restrict__ emb,
             float* __restrict__ out,
             int B) {
    const int b = blockIdx.x * blockDim.x + threadIdx.x;
    if (b >= B) return;

    // ---- context rho: branchless masked mean of per-token densities ----
    int toks[QC_S];
#pragma unroll
    for (int t = 0; t < QC_S; t++) toks[t] = contexts[b * QC_S + t];

    float ctx[QC_TRIL];
#pragma unroll
    for (int i = 0; i < QC_TRIL; i++) ctx[i] = 0.f;
    float cnt = 0.f;
#pragma unroll 2
    for (int t = 0; t < QC_S; t++) {
        const float m = (toks[t] != 0) ? 1.0f : 0.0f;
        cnt += m;
        add_density(emb + (long)toks[t] * QC_TRIL, ctx, m);
    }
    {
        const float ic = __fdividef(1.0f, cnt);  // cnt==0 -> inf, matches reference 0/0
#pragma unroll
        for (int i = 0; i < QC_TRIL; i++) ctx[i] *= ic;
    }

    // ---- target sigma ----
    float sig[QC_TRIL];
#pragma unroll
    for (int i = 0; i < QC_TRIL; i++) sig[i] = 0.f;
    add_density(emb + (long)targets[b] * QC_TRIL, sig, 1.0f);

    // ---- Cholesky of (ctx + 1e-6 I) = C C^T, rsqrt-based ----
    float C[QC_TRIL];
#pragma unroll
    for (int j = 0; j < QC_DIM; j++) {
        float d = ctx[sidx(j, j)] + 1e-6f;
#pragma unroll
        for (int k = 0; k < j; k++) d = fmaf(-C[sidx(j, k)], C[sidx(j, k)], d);
        d = fmaxf(d, 1e-14f);
        const float icjj = rsqrtf(d);
        C[sidx(j, j)] = d * icjj;
#pragma unroll
        for (int i = j + 1; i < QC_DIM; i++) {
            float v = ctx[sidx(i, j)];
#pragma unroll
            for (int k = 0; k < j; k++) v = fmaf(-C[sidx(i, k)], C[sidx(j, k)], v);
            C[sidx(i, j)] = v * icjj;
        }
    }

    // ---- W = C^T * sigma * C  (column-at-a-time; eig(W) = eig((ctx+eps I) sigma)) ----
    float W[QC_DIM][QC_DIM];
#pragma unroll
    for (int j = 0; j < QC_DIM; j++) {
        float tj[QC_DIM];  // column j of T = sigma * C
#pragma unroll
        for (int i = 0; i < QC_DIM; i++) {
            float s = 0.f;
#pragma unroll
            for (int k = j; k < QC_DIM; k++)      // C[k][j] nonzero for k>=j
                s = fmaf(sig[symi(i, k)], C[sidx(k, j)], s);
            tj[i] = s;
        }
#pragma unroll
        for (int i = 0; i <= j; i++) {
            float s = 0.f;
#pragma unroll
            for (int k = i; k < QC_DIM; k++)      // C[k][i] nonzero for k>=i
                s = fmaf(C[sidx(k, i)], tj[k], s);
            W[i][j] = s;
            W[j][i] = s;
        }
    }

    // ---- eigenvalues-only Jacobi, round-robin ordering: 4 independent pairs/round ----
#pragma unroll 1
    for (int sweep = 0; sweep < 6; sweep++) {
        // round 0: (7,0) (1,6) (2,5) (3,4)
        JROT(7, 0); JROT(1, 6); JROT(2, 5); JROT(3, 4);
        // round 1: (7,1) (2,0) (3,6) (4,5)
        JROT(7, 1); JROT(2, 0); JROT(3, 6); JROT(4, 5);
        // round 2: (7,2) (3,1) (4,0) (5,6)
        JROT(7, 2); JROT(3, 1); JROT(4, 0); JROT(5, 6);
        // round 3: (7,3) (4,2) (5,1) (6,0)
        JROT(7, 3); JROT(4, 2); JROT(5, 1); JROT(6, 0);
        // round 4: (7,4) (5,3) (6,2) (0,1)
        JROT(7, 4); JROT(5, 3); JROT(6, 2); JROT(0, 1);
        // round 5: (7,5) (6,4) (0,3) (1,2)
        JROT(7, 5); JROT(6, 4); JROT(0, 3); JROT(1, 2);
        // round 6: (7,6) (0,5) (1,4) (2,3)
        JROT(7, 6); JROT(0, 5); JROT(1, 4); JROT(2, 3);
    }

    // ---- f = sum sqrt(|eig| + eps); out = -log(clip(f)) ----
    float f = 0.f;
#pragma unroll
    for (int i = 0; i < QC_DIM; i++) {
        const float x = fabsf(W[i][i]) + 1e-6f;
        f = fmaf(x, rsqrtf(x), f);   // sqrt(x) = x * rsqrt(x), x >= 1e-6
    }
    f = fminf(f, 1.0f);
    f = fmaxf(f, 1e-8f);
    out[b] = -logf(f);
}

extern "C" void kernel_launch(void* const* d_in, const int* in_sizes, int n_in,
                              void* d_out, int out_size) {
    const int*   contexts = (const int*)d_in[0];   // [B, 10] int32
    const int*   targets  = (const int*)d_in[1];   // [B] int32
    const float* emb      = (const float*)d_in[2]; // [V, 36] float32
    float*       out      = (float*)d_out;         // [B] float32
    const int B = in_sizes[1];
    const int threads = 128;
    const int blocks = (B + threads - 1) / threads;
    qcbow_kernel<<<blocks, threads>>>(contexts, targets, emb, out, B);
}

// round 3
// speedup vs baseline: 2.0667x; 1.7467x over previous
#include <cuda_runtime.h>
#include <cuda_bf16.h>

// QuantumCBOW: B=16384, S=10, DIM=8, TRIL=36.
// R3: packed symmetric Jacobi (36-reg W, ~27 ops/rotation incl. closed-form
// diagonal), 5 sweeps, in-place Cholesky, minimized live register state.

#define QC_DIM  8
#define QC_TRIL 36
#define QC_S    10

__device__ __forceinline__ constexpr int sidx(int i, int j) { return i * (i + 1) / 2 + j; }
__device__ __forceinline__ constexpr int symi(int i, int j) { return (i >= j) ? sidx(i, j) : sidx(j, i); }

// Accumulate w * normalized-density(row) into acc[36] (lower-tri storage).
__device__ __forceinline__ void add_density(const float* __restrict__ row, float* acc, float wgt) {
    float L[QC_TRIL];
    const float4* r4 = reinterpret_cast<const float4*>(row);  // 36*4B rows, 16B aligned
#pragma unroll
    for (int v = 0; v < 9; v++) {
        float4 t = r4[v];
        L[4 * v + 0] = t.x; L[4 * v + 1] = t.y;
        L[4 * v + 2] = t.z; L[4 * v + 3] = t.w;
    }
#pragma unroll
    for (int i = 0; i < QC_DIM; i++) {
        const int d = sidx(i, i);
        L[d] = fmaxf(L[d], 1e-4f);
    }
    float tr = 0.f;
#pragma unroll
    for (int i = 0; i < QC_TRIL; i++) tr = fmaf(L[i], L[i], tr);
    const float inv = wgt * __fdividef(1.0f, tr + 1.7e-5f);
#pragma unroll
    for (int i = 0; i < QC_DIM; i++) {
#pragma unroll
        for (int j = 0; j <= i; j++) {
            float s = 0.f;
#pragma unroll
            for (int k = 0; k <= j; k++)
                s = fmaf(L[sidx(i, k)], L[sidx(j, k)], s);
            if (i == j) s += 2e-6f;  // eps + corr
            acc[sidx(i, j)] = fmaf(s, inv, acc[sidx(i, j)]);
        }
    }
}

// Packed-symmetric branchless Jacobi rotation on W[36], pair (p,q), p<q.
// Closed-form diagonal: app' = app - t*apq, aqq' = aqq + t*apq, apq' = 0.
#define JROT(p, q) do {                                                        \
    const float apq = W[sidx(q, p)];                                           \
    const float dd  = W[sidx(q, q)] - W[sidx(p, p)];                           \
    const float a2  = 2.0f * apq;                                              \
    const float vv  = fmaf(dd, dd, fmaf(a2, a2, 1e-30f));                      \
    const float u   = vv * rsqrtf(vv);                                         \
    const float t   = __fdividef(a2 * copysignf(1.0f, dd), fabsf(dd) + u);     \
    const float c   = rsqrtf(fmaf(t, t, 1.0f));                                \
    const float s   = t * c;                                                   \
    W[sidx(p, p)] = fmaf(-t, apq, W[sidx(p, p)]);                              \
    W[sidx(q, q)] = fmaf( t, apq, W[sidx(q, q)]);                              \
    W[sidx(q, p)] = 0.0f;                                                      \
    _Pragma("unroll")                                                          \
    for (int k = 0; k < QC_DIM; k++) {                                         \
        if (k != p && k != q) {                                                \
            const float akp = W[symi(k, p)];                                   \
            const float akq = W[symi(k, q)];                                   \
            W[symi(k, p)] = fmaf(c, akp, -s * akq);                            \
            W[symi(k, q)] = fmaf(s, akp,  c * akq);                            \
        }                                                                      \
    }                                                                          \
} while (0)

__global__ void __launch_bounds__(128, 1)
qcbow_kernel(const int* __restrict__ contexts,
             const int* __restrict__ targets,
             const float* __restrict__ emb,
             float* __restrict__ out,
             int B) {
    const int b = blockIdx.x * blockDim.x + threadIdx.x;
    if (b >= B) return;

    // ---- context rho: branchless masked mean of per-token densities ----
    float ctx[QC_TRIL];
#pragma unroll
    for (int i = 0; i < QC_TRIL; i++) ctx[i] = 0.f;
    float cnt = 0.f;
#pragma unroll 2
    for (int t = 0; t < QC_S; t++) {
        const int tok = contexts[b * QC_S + t];
        const float m = (tok != 0) ? 1.0f : 0.0f;
        cnt += m;
        add_density(emb + (long)tok * QC_TRIL, ctx, m);
    }
    {
        const float ic = __fdividef(1.0f, cnt);  // cnt==0 -> inf, matches reference 0/0
#pragma unroll
        for (int i = 0; i < QC_TRIL; i++) ctx[i] *= ic;
    }

    // ---- in-place Cholesky of (ctx + 1e-6 I): ctx becomes C with C C^T ----
#pragma unroll
    for (int j = 0; j < QC_DIM; j++) {
        float d = ctx[sidx(j, j)] + 1e-6f;
#pragma unroll
        for (int k = 0; k < j; k++) d = fmaf(-ctx[sidx(j, k)], ctx[sidx(j, k)], d);
        d = fmaxf(d, 1e-14f);
        const float icjj = rsqrtf(d);
        ctx[sidx(j, j)] = d * icjj;
#pragma unroll
        for (int i = j + 1; i < QC_DIM; i++) {
            float v = ctx[sidx(i, j)];
#pragma unroll
            for (int k = 0; k < j; k++) v = fmaf(-ctx[sidx(i, k)], ctx[sidx(j, k)], v);
            ctx[sidx(i, j)] = v * icjj;
        }
    }

    // ---- target sigma ----
    float sig[QC_TRIL];
#pragma unroll
    for (int i = 0; i < QC_TRIL; i++) sig[i] = 0.f;
    add_density(emb + (long)targets[b] * QC_TRIL, sig, 1.0f);

    // ---- W = C^T * sigma * C, packed lower-tri (eig(W) = eig((ctx+eps I) sigma)) ----
    float W[QC_TRIL];
#pragma unroll
    for (int j = 0; j < QC_DIM; j++) {
        float tj[QC_DIM];  // column j of T = sigma * C
#pragma unroll
        for (int i = 0; i < QC_DIM; i++) {
            float s = 0.f;
#pragma unroll
            for (int k = j; k < QC_DIM; k++)      // C[k][j] nonzero for k>=j
                s = fmaf(sig[symi(i, k)], ctx[sidx(k, j)], s);
            tj[i] = s;
        }
#pragma unroll
        for (int i = 0; i <= j; i++) {            // W[i][j], i<=j -> store at sidx(j,i)
            float s = 0.f;
#pragma unroll
            for (int k = i; k < QC_DIM; k++)      // C[k][i] nonzero for k>=i
                s = fmaf(ctx[sidx(k, i)], tj[k], s);
            W[sidx(j, i)] = s;
        }
    }

    // ---- eigenvalues-only packed Jacobi, round-robin: 4 disjoint pairs/round ----
#pragma unroll 1
    for (int sweep = 0; sweep < 5; sweep++) {
        JROT(0, 7); JROT(1, 6); JROT(2, 5); JROT(3, 4);
        JROT(1, 7); JROT(0, 2); JROT(3, 6); JROT(4, 5);
        JROT(2, 7); JROT(1, 3); JROT(0, 4); JROT(5, 6);
        JROT(3, 7); JROT(2, 4); JROT(1, 5); JROT(0, 6);
        JROT(4, 7); JROT(3, 5); JROT(2, 6); JROT(0, 1);
        JROT(5, 7); JROT(4, 6); JROT(0, 3); JROT(1, 2);
        JROT(6, 7); JROT(0, 5); JROT(1, 4); JROT(2, 3);
    }

    // ---- f = sum sqrt(|eig| + eps); out = -log(clip(f)) ----
    float f = 0.f;
#pragma unroll
    for (int i = 0; i < QC_DIM; i++) {
        const float x = fabsf(W[sidx(i, i)]) + 1e-6f;
        f = fmaf(x, rsqrtf(x), f);   // sqrt(x) = x * rsqrt(x), x >= 1e-6
    }
    f = fminf(f, 1.0f);
    f = fmaxf(f, 1e-8f);
    out[b] = -logf(f);
}

extern "C" void kernel_launch(void* const* d_in, const int* in_sizes, int n_in,
                              void* d_out, int out_size) {
    const int*   contexts = (const int*)d_in[0];   // [B, 10] int32
    const int*   targets  = (const int*)d_in[1];   // [B] int32
    const float* emb      = (const float*)d_in[2]; // [V, 36] float32
    float*       out      = (float*)d_out;         // [B] float32
    const int B = in_sizes[1];
    const int threads = 128;
    const int blocks = (B + threads - 1) / threads;
    qcbow_kernel<<<blocks, threads>>>(contexts, targets, emb, out, B);
}